// round 13
// baseline (speedup 1.0000x reference)
#include <cuda_runtime.h>
#include <cuda_fp16.h>
#include <cstdint>
#include <math.h>

#define NB    8
#define CIN   512
#define KCC   256
#define KK    19
#define HW    16384
#define TOT   (NB * HW)
#define EPSF  1e-5f

// ---------------------------------------------------------------------------
// Scratch: fp16 single-plane activations; x converted inline in G1.
// ---------------------------------------------------------------------------
__device__ __half g_t1[(size_t)KCC * TOT];
__device__ __half g_q [(size_t)KCC * TOT];
__device__ __half g_c [(size_t)KCC * TOT];
__device__ __half g_w1[KCC * CIN];
__device__ __half g_w2[KCC * KCC];
__device__ __half g_wu[CIN * KCC];
__device__ float  g_tbuf[NB * KCC * KK];
__device__ float  g_kbuf[NB * KCC * KK];
__device__ float  g_vbuf[NB * KCC * KK];

static __device__ __forceinline__ uint32_t smem_u32(const void* p) {
    uint32_t a;
    asm("{ .reg .u64 t; cvta.to.shared.u64 t, %1; cvt.u32.u64 %0, t; }"
        : "=r"(a) : "l"(p));
    return a;
}

#define LDSM4(r0, r1, r2, r3, addr) \
    asm volatile("ldmatrix.sync.aligned.m8n8.x4.shared.b16 {%0,%1,%2,%3}, [%4];" \
                 : "=r"(r0), "=r"(r1), "=r"(r2), "=r"(r3) : "r"(addr))

#define LDSM4T(r0, r1, r2, r3, addr) \
    asm volatile("ldmatrix.sync.aligned.m8n8.x4.trans.shared.b16 {%0,%1,%2,%3}, [%4];" \
                 : "=r"(r0), "=r"(r1), "=r"(r2), "=r"(r3) : "r"(addr))

#define MMAH(d, a, b) \
    asm volatile("mma.sync.aligned.m16n8k16.row.col.f32.f16.f16.f32 " \
                 "{%0,%1,%2,%3}, {%4,%5,%6,%7}, {%8,%9}, {%0,%1,%2,%3};" \
                 : "+f"((d)[0]), "+f"((d)[1]), "+f"((d)[2]), "+f"((d)[3]) \
                 : "r"((a)[0]), "r"((a)[1]), "r"((a)[2]), "r"((a)[3]), \
                   "r"((b)[0]), "r"((b)[1]))

#define CP_ASYNC16(dst, src) \
    asm volatile("cp.async.cg.shared.global [%0], [%1], 16;" :: "r"(dst), "l"(src))
#define CP_COMMIT()  asm volatile("cp.async.commit_group;")
#define CP_WAIT(n)   asm volatile("cp.async.wait_group %0;" :: "n"(n))

static __device__ __forceinline__ uint32_t h2u(__half2 h) {
    return *reinterpret_cast<uint32_t*>(&h);
}
static __device__ __forceinline__ uint4 cvt8(const float4& a, const float4& b) {
    __half2 h0 = __floats2half2_rn(a.x, a.y);
    __half2 h1 = __floats2half2_rn(a.z, a.w);
    __half2 h2 = __floats2half2_rn(b.x, b.y);
    __half2 h3 = __floats2half2_rn(b.z, b.w);
    return make_uint4(h2u(h0), h2u(h1), h2u(h2), h2u(h3));
}

// ---------------------------------------------------------------------------
// fp32 -> fp16 plane (weights only; tiny)
// ---------------------------------------------------------------------------
__global__ void __launch_bounds__(256) cvt16_kernel(
    const float* __restrict__ s, __half* __restrict__ h, size_t n4)
{
    size_t idx = (size_t)blockIdx.x * 256 + threadIdx.x;
    if (idx >= n4) return;
    float4 v = ((const float4*)s)[idx];
    ((__half2*)h)[2 * idx]     = __floats2half2_rn(v.x, v.y);
    ((__half2*)h)[2 * idx + 1] = __floats2half2_rn(v.z, v.w);
}

// ---------------------------------------------------------------------------
// Proxy stage 1: t = bn_relu(w_o1 @ proxy_n), v = bn_relu(w_d @ proxy_n)
// ---------------------------------------------------------------------------
__global__ void __launch_bounds__(256) proxy1_kernel(
    const float* __restrict__ proxy,
    const float* __restrict__ w_o1, const float* __restrict__ o1g,
    const float* __restrict__ o1b,  const float* __restrict__ o1m,
    const float* __restrict__ o1v,
    const float* __restrict__ w_d,  const float* __restrict__ dgv,
    const float* __restrict__ dbv,  const float* __restrict__ dmv,
    const float* __restrict__ dvv)
{
    __shared__ float p_sh[CIN * KK];
    const int n   = blockIdx.y;
    const int ch0 = blockIdx.x * 32;
    const float* p = proxy + (size_t)n * CIN * KK;
    for (int i = threadIdx.x; i < CIN * KK; i += 256) p_sh[i] = p[i];
    __syncthreads();

    const int chl = threadIdx.x >> 3;
    const int jg  = threadIdx.x & 7;
    const int ch  = ch0 + chl;

    float a1[3] = {0.f, 0.f, 0.f}, av[3] = {0.f, 0.f, 0.f};
    const float* w1r = w_o1 + (size_t)ch * CIN;
    const float* wdr = w_d  + (size_t)ch * CIN;
    for (int c = 0; c < CIN; c++) {
        const float w1 = __ldg(&w1r[c]);
        const float wd = __ldg(&wdr[c]);
        const float* pc = p_sh + c * KK;
#pragma unroll
        for (int u = 0; u < 3; u++) {
            const int j = jg + 8 * u;
            if (j < KK) {
                const float pv = pc[j];
                a1[u] = fmaf(w1, pv, a1[u]);
                av[u] = fmaf(wd, pv, av[u]);
            }
        }
    }
    {
        const float inv = o1g[ch] * rsqrtf(o1v[ch] + EPSF);
        const float bt  = o1b[ch] - o1m[ch] * inv;
#pragma unroll
        for (int u = 0; u < 3; u++) {
            const int j = jg + 8 * u;
            if (j < KK)
                g_tbuf[((size_t)n * KCC + ch) * KK + j] = fmaxf(fmaf(a1[u], inv, bt), 0.f);
        }
    }
    {
        const float inv = dgv[ch] * rsqrtf(dvv[ch] + EPSF);
        const float bt  = dbv[ch] - dmv[ch] * inv;
#pragma unroll
        for (int u = 0; u < 3; u++) {
            const int j = jg + 8 * u;
            if (j < KK)
                g_vbuf[((size_t)n * KCC + ch) * KK + j] = fmaxf(fmaf(av[u], inv, bt), 0.f);
        }
    }
}

// ---------------------------------------------------------------------------
// Proxy stage 2: k = bn_relu(w_o2 @ t_n)
// ---------------------------------------------------------------------------
__global__ void __launch_bounds__(256) proxy2_kernel(
    const float* __restrict__ w_o2, const float* __restrict__ o2g,
    const float* __restrict__ o2b,  const float* __restrict__ o2m,
    const float* __restrict__ o2v)
{
    __shared__ float t_sh[KCC * KK];
    const int n   = blockIdx.y;
    const int ch0 = blockIdx.x * 32;
    for (int i = threadIdx.x; i < KCC * KK; i += 256)
        t_sh[i] = g_tbuf[(size_t)n * KCC * KK + i];
    __syncthreads();

    const int chl = threadIdx.x >> 3;
    const int jg  = threadIdx.x & 7;
    const int ch  = ch0 + chl;

    float a2[3] = {0.f, 0.f, 0.f};
    const float* w2r = w_o2 + (size_t)ch * KCC;
    for (int c = 0; c < KCC; c++) {
        const float w2 = __ldg(&w2r[c]);
        const float* tc = t_sh + c * KK;
#pragma unroll
        for (int u = 0; u < 3; u++) {
            const int j = jg + 8 * u;
            if (j < KK) a2[u] = fmaf(w2, tc[j], a2[u]);
        }
    }
    const float inv = o2g[ch] * rsqrtf(o2v[ch] + EPSF);
    const float bt  = o2b[ch] - o2m[ch] * inv;
#pragma unroll
    for (int u = 0; u < 3; u++) {
        const int j = jg + 8 * u;
        if (j < KK)
            g_kbuf[((size_t)n * KCC + ch) * KK + j] = fmaxf(fmaf(a2[u], inv, bt), 0.f);
    }
}

// ---------------------------------------------------------------------------
// HMMA fp16 GEMM: D = bn_relu( W @ B ).
// BM=256 BN=128 BK=32, 256 threads, 1 CTA/SM, cp.async double-buffered,
// warp tile 64x64 (warp grid 4m x 2n) — R4-proven high-rate shape.
// blockIdx.x = M tile (fast -> B L2 reuse across M passes).
// BIN  0: B fp16 (cp.async); 1: B fp32 (reg load one stage ahead, convert @ STS).
// BOUT 0: fp16 plane out;    1: fp32 out.
// stage: A 16K | B 8K = 24K; 2 stages = 48K dynamic.
// ---------------------------------------------------------------------------
#define OFF_A  0
#define OFF_B  16384
#define STG    24576
#define GEMM_SMEM (2 * STG)

template <int BIN, int BOUT>
__global__ void __launch_bounds__(256, 1) gemm_mma(
    const __half* __restrict__ A, int KT,
    const __half* __restrict__ Bh, const float* __restrict__ Bf,
    int bRow, long bBatch,
    float* __restrict__ Cf, __half* __restrict__ Ch,
    int cRow, long cBatch,
    const float* __restrict__ gg, const float* __restrict__ bb,
    const float* __restrict__ mm, const float* __restrict__ vv)
{
    extern __shared__ __align__(128) unsigned char sm[];
    const uint32_t sb = smem_u32(sm);

    const int tid  = threadIdx.x;
    const int lane = tid & 31;
    const int w    = tid >> 5;
    const int mw   = (w >> 1) * 64;     // 4 m-warps
    const int nw   = (w & 1) * 64;      // 2 n-warps

    const int mBase = blockIdx.x * 256;
    const int nBase = blockIdx.y * 128;
    const int nbat  = nBase >> 14;
    const int hw0   = nBase & (HW - 1);

    const __half* Bph = (BIN == 0) ? Bh + (size_t)nbat * bBatch + hw0 : nullptr;
    const float*  Bpf = (BIN == 1) ? Bf + (size_t)nbat * bBatch + hw0 : nullptr;

    // staging indices: A = one 64B row per thread (4 chunks); B as before
    const int bk   = tid >> 3;          // 0..31
    const int bu0  = (tid & 7) * 2;     // chunk pair in 256B row

    float acc[4][8][4];
#pragma unroll
    for (int i = 0; i < 4; i++)
#pragma unroll
        for (int g = 0; g < 8; g++)
#pragma unroll
            for (int r = 0; r < 4; r++) acc[i][g][r] = 0.f;

    const int nIt = KT / 32;

    float4 pbf[4];                      // BIN==1: 2 chunks x 8 floats

    auto loadB = [&](int k0) {
        if (BIN == 1) {
#pragma unroll
            for (int j = 0; j < 2; j++) {
                const float* src = Bpf + (size_t)(k0 + bk) * bRow + (bu0 + j) * 8;
                pbf[2 * j]     = *(const float4*)src;
                pbf[2 * j + 1] = *(const float4*)(src + 4);
            }
        }
    };
    auto stsB = [&](int buf) {
        if (BIN == 1) {
#pragma unroll
            for (int j = 0; j < 2; j++) {
                const int u = bu0 + j;
                const uint32_t off = (uint32_t)(bk * 256 + ((u ^ (bk & 7)) << 4));
                *(uint4*)(sm + buf * STG + OFF_B + off) = cvt8(pbf[2 * j], pbf[2 * j + 1]);
            }
        }
    };

    auto issue = [&](int buf, int k0) {
        const uint32_t base = sb + buf * STG;
        const __half* ar = A + (size_t)(mBase + tid) * KT + k0;
#pragma unroll
        for (int q = 0; q < 4; q++) {
            const uint32_t off = (uint32_t)(tid * 64 + ((q ^ ((tid >> 1) & 3)) << 4));
            CP_ASYNC16(base + OFF_A + off, ar + q * 8);
        }
        if (BIN == 0) {
#pragma unroll
            for (int j = 0; j < 2; j++) {
                const int u = bu0 + j;
                const uint32_t off = (uint32_t)(bk * 256 + ((u ^ (bk & 7)) << 4));
                CP_ASYNC16(base + OFF_B + off, Bph + (size_t)(k0 + bk) * bRow + u * 8);
            }
        }
    };

    // prologue
    loadB(0);
    issue(0, 0);
    CP_COMMIT();
    stsB(0);
    if (nIt > 1) loadB(32);

    for (int i = 0; i < nIt; i++) {
        if (i + 1 < nIt) {
            issue((i + 1) & 1, (i + 1) * 32);
            CP_COMMIT();
            CP_WAIT(1);
        } else {
            CP_WAIT(0);
        }
        __syncthreads();
        if (i + 1 < nIt) {
            stsB((i + 1) & 1);              // buffer (i+1)&1 last read at iter i-1
            if (i + 2 < nIt) loadB((i + 2) * 32);
        }

        const uint32_t base = sb + (i & 1) * STG;
#pragma unroll
        for (int kk = 0; kk < 32; kk += 16) {
            uint32_t ah[4][4], bh[8][2];
            const int arw = lane & 15;
            const int acl = kk + (lane >> 4) * 8;
            const int krw = kk + (lane & 15);
            const int nch = (lane >> 4) * 8;

            // B: 4 LDSM4T cover 64 n-cols
#pragma unroll
            for (int ni = 0; ni < 4; ni++) {
                const int nn = nw + ni * 16 + nch;
                const uint32_t bo = (uint32_t)(krw * 256 + ((((nn >> 3) ^ (krw & 7))) << 4));
                LDSM4T(bh[2 * ni][0], bh[2 * ni][1], bh[2 * ni + 1][0], bh[2 * ni + 1][1],
                       base + OFF_B + bo);
            }
            // A: 4 LDSM4 cover 64 m-rows
#pragma unroll
            for (int mi = 0; mi < 4; mi++) {
                const int r = mw + mi * 16 + arw;
                const uint32_t ao = (uint32_t)(r * 64 + ((((acl >> 3) ^ ((r >> 1) & 3))) << 4));
                LDSM4(ah[mi][0], ah[mi][1], ah[mi][2], ah[mi][3], base + OFF_A + ao);
            }
#pragma unroll
            for (int mi = 0; mi < 4; mi++)
#pragma unroll
                for (int g = 0; g < 8; g++) MMAH(acc[mi][g], ah[mi], bh[g]);
        }
        __syncthreads();
    }

    // ---- epilogue: BN + ReLU ----
#pragma unroll
    for (int mi = 0; mi < 4; mi++) {
        const int m_t = mBase + mw + mi * 16 + (lane >> 2);
        const int m_b = m_t + 8;
        const float inv_t = gg[m_t] * rsqrtf(vv[m_t] + EPSF);
        const float bt_t  = bb[m_t] - mm[m_t] * inv_t;
        const float inv_b = gg[m_b] * rsqrtf(vv[m_b] + EPSF);
        const float bt_b  = bb[m_b] - mm[m_b] * inv_b;
#pragma unroll
        for (int g = 0; g < 8; g++) {
            const int hw = hw0 + nw + g * 8 + 2 * (lane & 3);
            float vtx = fmaxf(fmaf(acc[mi][g][0], inv_t, bt_t), 0.f);
            float vty = fmaxf(fmaf(acc[mi][g][1], inv_t, bt_t), 0.f);
            float vbx = fmaxf(fmaf(acc[mi][g][2], inv_b, bt_b), 0.f);
            float vby = fmaxf(fmaf(acc[mi][g][3], inv_b, bt_b), 0.f);
            if (BOUT == 1) {
                float* rowT = Cf + (size_t)nbat * cBatch + (size_t)m_t * cRow;
                float* rowB = Cf + (size_t)nbat * cBatch + (size_t)m_b * cRow;
                *(float2*)(rowT + hw) = make_float2(vtx, vty);
                *(float2*)(rowB + hw) = make_float2(vbx, vby);
            } else {
                size_t oT = (size_t)nbat * cBatch + (size_t)m_t * cRow + hw;
                size_t oB = (size_t)nbat * cBatch + (size_t)m_b * cRow + hw;
                *(__half2*)(Ch + oT) = __floats2half2_rn(vtx, vty);
                *(__half2*)(Ch + oB) = __floats2half2_rn(vbx, vby);
            }
        }
    }
}

// ---------------------------------------------------------------------------
// Attention: 256 threads, 2 adjacent pixels/thread; q fp16 plane in,
// ctx fp16 plane out. k/v fp32 in smem.
// ---------------------------------------------------------------------------
__global__ void __launch_bounds__(256) attn_kernel(
    const __half* __restrict__ qh, __half* __restrict__ ch)
{
    __shared__ float k_sh[KCC * KK];
    __shared__ float v_sh[KCC * KK];
    const int pixBase = blockIdx.x * 512;
    const int n = pixBase >> 14;
    for (int i = threadIdx.x; i < KCC * KK; i += 256) {
        k_sh[i] = g_kbuf[(size_t)n * KCC * KK + i];
        v_sh[i] = g_vbuf[(size_t)n * KCC * KK + i];
    }
    __syncthreads();

    const int p0 = pixBase + 2 * threadIdx.x;

    float s0[KK], s1[KK];
#pragma unroll
    for (int j = 0; j < KK; j++) { s0[j] = 0.f; s1[j] = 0.f; }

    for (int c = 0; c < KCC; c++) {
        size_t o = (size_t)c * TOT + p0;
        float2 fq = __half22float2(*(const __half2*)(qh + o));
#pragma unroll
        for (int j = 0; j < KK; j++) {
            const float kc = k_sh[c * KK + j];
            s0[j] = fmaf(fq.x, kc, s0[j]);
            s1[j] = fmaf(fq.y, kc, s1[j]);
        }
    }

    {
        float mx0 = -1e30f, mx1 = -1e30f;
#pragma unroll
        for (int j = 0; j < KK; j++) {
            s0[j] *= 0.0625f; s1[j] *= 0.0625f;
            mx0 = fmaxf(mx0, s0[j]); mx1 = fmaxf(mx1, s1[j]);
        }
        float t0 = 0.f, t1 = 0.f;
#pragma unroll
        for (int j = 0; j < KK; j++) {
            s0[j] = __expf(s0[j] - mx0); t0 += s0[j];
            s1[j] = __expf(s1[j] - mx1); t1 += s1[j];
        }
        const float r0 = 1.f / t0, r1 = 1.f / t1;
#pragma unroll
        for (int j = 0; j < KK; j++) { s0[j] *= r0; s1[j] *= r1; }
    }

    for (int c = 0; c < KCC; c++) {
        float a0 = 0.f, a1 = 0.f;
#pragma unroll
        for (int j = 0; j < KK; j++) {
            const float vc = v_sh[c * KK + j];
            a0 = fmaf(s0[j], vc, a0);
            a1 = fmaf(s1[j], vc, a1);
        }
        size_t o = (size_t)c * TOT + p0;
        *(__half2*)(ch + o) = __floats2half2_rn(a0, a1);
    }
}

// ---------------------------------------------------------------------------
// Launch
// ---------------------------------------------------------------------------
extern "C" void kernel_launch(void* const* d_in, const int* in_sizes, int n_in,
                              void* d_out, int out_size)
{
    const float* x     = (const float*)d_in[0];
    const float* proxy = (const float*)d_in[1];

    const float *w_p1, *w_p2, *w_o1, *w_o2, *w_d, *w_u;
    const float *p1g,*p1b,*p1m,*p1v, *p2g,*p2b,*p2m,*p2v;
    const float *o1g,*o1b,*o1m,*o1v, *o2g,*o2b,*o2m,*o2v;
    const float *dg,*db,*dm,*dv, *ug,*ub,*um,*uv;

    if (in_sizes[3] == KCC * KCC) {
        w_p1=(const float*)d_in[2]; w_p2=(const float*)d_in[3];
        w_o1=(const float*)d_in[4]; w_o2=(const float*)d_in[5];
        w_d =(const float*)d_in[6]; w_u =(const float*)d_in[7];
        p1g=(const float*)d_in[8];  p1b=(const float*)d_in[9];
        p1m=(const float*)d_in[10]; p1v=(const float*)d_in[11];
        p2g=(const float*)d_in[12]; p2b=(const float*)d_in[13];
        p2m=(const float*)d_in[14]; p2v=(const float*)d_in[15];
        o1g=(const float*)d_in[16]; o1b=(const float*)d_in[17];
        o1m=(const float*)d_in[18]; o1v=(const float*)d_in[19];
        o2g=(const float*)d_in[20]; o2b=(const float*)d_in[21];
        o2m=(const float*)d_in[22]; o2v=(const float*)d_in[23];
        dg =(const float*)d_in[24]; db =(const float*)d_in[25];
        dm =(const float*)d_in[26]; dv =(const float*)d_in[27];
        ug =(const float*)d_in[28]; ub =(const float*)d_in[29];
        um =(const float*)d_in[30]; uv =(const float*)d_in[31];
    } else {
        w_p1=(const float*)d_in[2];
        p1g=(const float*)d_in[3];  p1b=(const float*)d_in[4];
        p1m=(const float*)d_in[5];  p1v=(const float*)d_in[6];
        w_p2=(const float*)d_in[7];
        p2g=(const float*)d_in[8];  p2b=(const float*)d_in[9];
        p2m=(const float*)d_in[10]; p2v=(const float*)d_in[11];
        w_o1=(const float*)d_in[12];
        o1g=(const float*)d_in[13]; o1b=(const float*)d_in[14];
        o1m=(const float*)d_in[15]; o1v=(const float*)d_in[16];
        w_o2=(const float*)d_in[17];
        o2g=(const float*)d_in[18]; o2b=(const float*)d_in[19];
        o2m=(const float*)d_in[20]; o2v=(const float*)d_in[21];
        w_d =(const float*)d_in[22];
        dg =(const float*)d_in[23]; db =(const float*)d_in[24];
        dm =(const float*)d_in[25]; dv =(const float*)d_in[26];
        w_u =(const float*)d_in[27];
        ug =(const float*)d_in[28]; ub =(const float*)d_in[29];
        um =(const float*)d_in[30]; uv =(const float*)d_in[31];
    }

    float* out = (float*)d_out;

    __half *t1p,*qp,*cp,*w1p,*w2p,*wup;
    cudaGetSymbolAddress((void**)&t1p, g_t1);
    cudaGetSymbolAddress((void**)&qp,  g_q);
    cudaGetSymbolAddress((void**)&cp,  g_c);
    cudaGetSymbolAddress((void**)&w1p, g_w1);
    cudaGetSymbolAddress((void**)&w2p, g_w2);
    cudaGetSymbolAddress((void**)&wup, g_wu);

    cudaFuncSetAttribute(gemm_mma<1, 0>, cudaFuncAttributeMaxDynamicSharedMemorySize, GEMM_SMEM);
    cudaFuncSetAttribute(gemm_mma<0, 0>, cudaFuncAttributeMaxDynamicSharedMemorySize, GEMM_SMEM);
    cudaFuncSetAttribute(gemm_mma<0, 1>, cudaFuncAttributeMaxDynamicSharedMemorySize, GEMM_SMEM);

    // 0) convert weights to fp16 (tiny)
    cvt16_kernel<<<(KCC * CIN / 4 + 255) / 256, 256>>>(w_p1, w1p, KCC * CIN / 4);
    cvt16_kernel<<<(KCC * KCC / 4 + 255) / 256, 256>>>(w_p2, w2p, KCC * KCC / 4);
    cvt16_kernel<<<(CIN * KCC / 4 + 255) / 256, 256>>>(w_u,  wup, CIN * KCC / 4);

    // 1) proxy path
    proxy1_kernel<<<dim3(8, NB), 256>>>(proxy,
        w_o1, o1g, o1b, o1m, o1v,
        w_d,  dg,  db,  dm,  dv);
    proxy2_kernel<<<dim3(8, NB), 256>>>(w_o2, o2g, o2b, o2m, o2v);

    // 2) t1 = bn_relu(w_p1 @ x)  (x fp32 converted at STS) -> fp16 plane
    gemm_mma<1, 0><<<dim3(KCC / 256, TOT / 128), 256, GEMM_SMEM>>>(
        w1p, CIN,
        nullptr, x, HW, (long)CIN * HW,
        nullptr, t1p, TOT, HW,
        p1g, p1b, p1m, p1v);

    // 3) q = bn_relu(w_p2 @ t1) -> fp16 plane
    gemm_mma<0, 0><<<dim3(KCC / 256, TOT / 128), 256, GEMM_SMEM>>>(
        w2p, KCC,
        t1p, nullptr, TOT, HW,
        nullptr, qp, TOT, HW,
        p2g, p2b, p2m, p2v);

    // 4) attention q -> ctx fp16 plane
    attn_kernel<<<TOT / 512, 256>>>(qp, cp);

    // 5) out = bn_relu(w_u @ ctx) -> fp32 NCHW
    gemm_mma<0, 1><<<dim3(CIN / 256, TOT / 128), 256, GEMM_SMEM>>>(
        wup, KCC,
        cp, nullptr, TOT, HW,
        out, nullptr, HW, (long)CIN * HW,
        ug, ub, um, uv);
}

// round 15
// speedup vs baseline: 1.1234x; 1.1234x over previous
#include <cuda_runtime.h>
#include <cuda_fp16.h>
#include <cstdint>
#include <math.h>

#define NB    8
#define CIN   512
#define KCC   256
#define KK    19
#define HW    16384
#define TOT   (NB * HW)
#define EPSF  1e-5f

// ---------------------------------------------------------------------------
// Scratch: fp16 single-plane activations; x converted inline in G1.
// ---------------------------------------------------------------------------
__device__ __half g_t1[(size_t)KCC * TOT];
__device__ __half g_q [(size_t)KCC * TOT];
__device__ __half g_c [(size_t)KCC * TOT];
__device__ __half g_w1[KCC * CIN];
__device__ __half g_w2[KCC * KCC];
__device__ __half g_wu[CIN * KCC];
__device__ float  g_tbuf[NB * KCC * KK];
__device__ float  g_kbuf[NB * KCC * KK];
__device__ float  g_vbuf[NB * KCC * KK];

static __device__ __forceinline__ uint32_t smem_u32(const void* p) {
    uint32_t a;
    asm("{ .reg .u64 t; cvta.to.shared.u64 t, %1; cvt.u32.u64 %0, t; }"
        : "=r"(a) : "l"(p));
    return a;
}

#define LDSM4(r0, r1, r2, r3, addr) \
    asm volatile("ldmatrix.sync.aligned.m8n8.x4.shared.b16 {%0,%1,%2,%3}, [%4];" \
                 : "=r"(r0), "=r"(r1), "=r"(r2), "=r"(r3) : "r"(addr))

#define LDSM4T(r0, r1, r2, r3, addr) \
    asm volatile("ldmatrix.sync.aligned.m8n8.x4.trans.shared.b16 {%0,%1,%2,%3}, [%4];" \
                 : "=r"(r0), "=r"(r1), "=r"(r2), "=r"(r3) : "r"(addr))

#define MMAH(d, a, b) \
    asm volatile("mma.sync.aligned.m16n8k16.row.col.f32.f16.f16.f32 " \
                 "{%0,%1,%2,%3}, {%4,%5,%6,%7}, {%8,%9}, {%0,%1,%2,%3};" \
                 : "+f"((d)[0]), "+f"((d)[1]), "+f"((d)[2]), "+f"((d)[3]) \
                 : "r"((a)[0]), "r"((a)[1]), "r"((a)[2]), "r"((a)[3]), \
                   "r"((b)[0]), "r"((b)[1]))

#define CP_ASYNC16(dst, src) \
    asm volatile("cp.async.cg.shared.global [%0], [%1], 16;" :: "r"(dst), "l"(src))
#define CP_COMMIT()  asm volatile("cp.async.commit_group;")
#define CP_WAIT(n)   asm volatile("cp.async.wait_group %0;" :: "n"(n))

static __device__ __forceinline__ uint32_t h2u(__half2 h) {
    return *reinterpret_cast<uint32_t*>(&h);
}
static __device__ __forceinline__ uint4 cvt8(const float4& a, const float4& b) {
    __half2 h0 = __floats2half2_rn(a.x, a.y);
    __half2 h1 = __floats2half2_rn(a.z, a.w);
    __half2 h2 = __floats2half2_rn(b.x, b.y);
    __half2 h3 = __floats2half2_rn(b.z, b.w);
    return make_uint4(h2u(h0), h2u(h1), h2u(h2), h2u(h3));
}

// ---------------------------------------------------------------------------
// fp32 -> fp16 plane (weights only; tiny)
// ---------------------------------------------------------------------------
__global__ void __launch_bounds__(256) cvt16_kernel(
    const float* __restrict__ s, __half* __restrict__ h, size_t n4)
{
    size_t idx = (size_t)blockIdx.x * 256 + threadIdx.x;
    if (idx >= n4) return;
    float4 v = ((const float4*)s)[idx];
    ((__half2*)h)[2 * idx]     = __floats2half2_rn(v.x, v.y);
    ((__half2*)h)[2 * idx + 1] = __floats2half2_rn(v.z, v.w);
}

// ---------------------------------------------------------------------------
// Proxy stage 1: t = bn_relu(w_o1 @ proxy_n), v = bn_relu(w_d @ proxy_n)
// ---------------------------------------------------------------------------
__global__ void __launch_bounds__(256) proxy1_kernel(
    const float* __restrict__ proxy,
    const float* __restrict__ w_o1, const float* __restrict__ o1g,
    const float* __restrict__ o1b,  const float* __restrict__ o1m,
    const float* __restrict__ o1v,
    const float* __restrict__ w_d,  const float* __restrict__ dgv,
    const float* __restrict__ dbv,  const float* __restrict__ dmv,
    const float* __restrict__ dvv)
{
    __shared__ float p_sh[CIN * KK];
    const int n   = blockIdx.y;
    const int ch0 = blockIdx.x * 32;
    const float* p = proxy + (size_t)n * CIN * KK;
    for (int i = threadIdx.x; i < CIN * KK; i += 256) p_sh[i] = p[i];
    __syncthreads();

    const int chl = threadIdx.x >> 3;
    const int jg  = threadIdx.x & 7;
    const int ch  = ch0 + chl;

    float a1[3] = {0.f, 0.f, 0.f}, av[3] = {0.f, 0.f, 0.f};
    const float* w1r = w_o1 + (size_t)ch * CIN;
    const float* wdr = w_d  + (size_t)ch * CIN;
    for (int c = 0; c < CIN; c++) {
        const float w1 = __ldg(&w1r[c]);
        const float wd = __ldg(&wdr[c]);
        const float* pc = p_sh + c * KK;
#pragma unroll
        for (int u = 0; u < 3; u++) {
            const int j = jg + 8 * u;
            if (j < KK) {
                const float pv = pc[j];
                a1[u] = fmaf(w1, pv, a1[u]);
                av[u] = fmaf(wd, pv, av[u]);
            }
        }
    }
    {
        const float inv = o1g[ch] * rsqrtf(o1v[ch] + EPSF);
        const float bt  = o1b[ch] - o1m[ch] * inv;
#pragma unroll
        for (int u = 0; u < 3; u++) {
            const int j = jg + 8 * u;
            if (j < KK)
                g_tbuf[((size_t)n * KCC + ch) * KK + j] = fmaxf(fmaf(a1[u], inv, bt), 0.f);
        }
    }
    {
        const float inv = dgv[ch] * rsqrtf(dvv[ch] + EPSF);
        const float bt  = dbv[ch] - dmv[ch] * inv;
#pragma unroll
        for (int u = 0; u < 3; u++) {
            const int j = jg + 8 * u;
            if (j < KK)
                g_vbuf[((size_t)n * KCC + ch) * KK + j] = fmaxf(fmaf(av[u], inv, bt), 0.f);
        }
    }
}

// ---------------------------------------------------------------------------
// Proxy stage 2: k = bn_relu(w_o2 @ t_n)
// ---------------------------------------------------------------------------
__global__ void __launch_bounds__(256) proxy2_kernel(
    const float* __restrict__ w_o2, const float* __restrict__ o2g,
    const float* __restrict__ o2b,  const float* __restrict__ o2m,
    const float* __restrict__ o2v)
{
    __shared__ float t_sh[KCC * KK];
    const int n   = blockIdx.y;
    const int ch0 = blockIdx.x * 32;
    for (int i = threadIdx.x; i < KCC * KK; i += 256)
        t_sh[i] = g_tbuf[(size_t)n * KCC * KK + i];
    __syncthreads();

    const int chl = threadIdx.x >> 3;
    const int jg  = threadIdx.x & 7;
    const int ch  = ch0 + chl;

    float a2[3] = {0.f, 0.f, 0.f};
    const float* w2r = w_o2 + (size_t)ch * KCC;
    for (int c = 0; c < KCC; c++) {
        const float w2 = __ldg(&w2r[c]);
        const float* tc = t_sh + c * KK;
#pragma unroll
        for (int u = 0; u < 3; u++) {
            const int j = jg + 8 * u;
            if (j < KK) a2[u] = fmaf(w2, tc[j], a2[u]);
        }
    }
    const float inv = o2g[ch] * rsqrtf(o2v[ch] + EPSF);
    const float bt  = o2b[ch] - o2m[ch] * inv;
#pragma unroll
    for (int u = 0; u < 3; u++) {
        const int j = jg + 8 * u;
        if (j < KK)
            g_kbuf[((size_t)n * KCC + ch) * KK + j] = fmaxf(fmaf(a2[u], inv, bt), 0.f);
    }
}

// ---------------------------------------------------------------------------
// HMMA fp16 GEMM: D = bn_relu( W @ B )  — R12 structure, 3-stage pipeline,
// ONE __syncthreads per K-iter.
// BM=128 BN=128 BK=32, 256 threads, 2 CTAs/SM, warp tile 64x32 (2m x 4n).
// blockIdx.x = M tile (fast -> B L2 reuse).
// BIN  0: B fp16 (cp.async); 1: B fp32 (reg load two stages ahead, STS convert).
// BOUT 0: fp16 plane out;    1: fp32 out.
// stage: A 8K | B 8K = 16K; 3 stages = 48K dynamic (x2 CTAs = 96K/SM).
// ---------------------------------------------------------------------------
#define OFF_A  0
#define OFF_B  8192
#define STG    16384
#define GEMM_SMEM (3 * STG)

template <int BIN, int BOUT>
__global__ void __launch_bounds__(256, 2) gemm_mma(
    const __half* __restrict__ A, int KT,
    const __half* __restrict__ Bh, const float* __restrict__ Bf,
    int bRow, long bBatch,
    float* __restrict__ Cf, __half* __restrict__ Ch,
    int cRow, long cBatch,
    const float* __restrict__ gg, const float* __restrict__ bb,
    const float* __restrict__ mm, const float* __restrict__ vv)
{
    extern __shared__ __align__(128) unsigned char sm[];
    const uint32_t sb = smem_u32(sm);

    const int tid  = threadIdx.x;
    const int lane = tid & 31;
    const int w    = tid >> 5;
    const int mw   = (w >> 2) * 64;     // 2 m-warps
    const int nw   = (w & 3) * 32;      // 4 n-warps

    const int mBase = blockIdx.x * 128;
    const int nBase = blockIdx.y * 128;
    const int nbat  = nBase >> 14;
    const int hw0   = nBase & (HW - 1);

    const __half* Bph = (BIN == 0) ? Bh + (size_t)nbat * bBatch + hw0 : nullptr;
    const float*  Bpf = (BIN == 1) ? Bf + (size_t)nbat * bBatch + hw0 : nullptr;

    // staging indices
    const int arow = tid >> 1;          // 0..127
    const int aq0  = (tid & 1) * 2;     // chunk pair in 64B row
    const int bk   = tid >> 3;          // 0..31
    const int bu0  = (tid & 7) * 2;     // chunk pair in 256B row

    float acc[4][4][4];
#pragma unroll
    for (int i = 0; i < 4; i++)
#pragma unroll
        for (int g = 0; g < 4; g++)
#pragma unroll
            for (int r = 0; r < 4; r++) acc[i][g][r] = 0.f;

    const int nIt = KT / 32;

    float4 pbf[4];                      // BIN==1: 2 chunks x 8 floats

    auto loadB = [&](int k0) {
        if (BIN == 1) {
#pragma unroll
            for (int j = 0; j < 2; j++) {
                const float* src = Bpf + (size_t)(k0 + bk) * bRow + (bu0 + j) * 8;
                pbf[2 * j]     = *(const float4*)src;
                pbf[2 * j + 1] = *(const float4*)(src + 4);
            }
        }
    };
    auto stsB = [&](int buf) {
        if (BIN == 1) {
#pragma unroll
            for (int j = 0; j < 2; j++) {
                const int u = bu0 + j;
                const uint32_t off = (uint32_t)(bk * 256 + ((u ^ (bk & 7)) << 4));
                *(uint4*)(sm + buf * STG + OFF_B + off) = cvt8(pbf[2 * j], pbf[2 * j + 1]);
            }
        }
    };
    auto issue = [&](int buf, int k0) {
        const uint32_t base = sb + buf * STG;
        const __half* ar = A + (size_t)(mBase + arow) * KT + k0;
#pragma unroll
        for (int j = 0; j < 2; j++) {
            const int q = aq0 + j;
            const uint32_t off = (uint32_t)(arow * 64 + ((q ^ ((arow >> 1) & 3)) << 4));
            CP_ASYNC16(base + OFF_A + off, ar + q * 8);
        }
        if (BIN == 0) {
#pragma unroll
            for (int j = 0; j < 2; j++) {
                const int u = bu0 + j;
                const uint32_t off = (uint32_t)(bk * 256 + ((u ^ (bk & 7)) << 4));
                CP_ASYNC16(base + OFF_B + off, Bph + (size_t)(k0 + bk) * bRow + u * 8);
            }
        }
    };

    // prologue: stages 0 and 1
    loadB(0);
    issue(0, 0);
    CP_COMMIT();
    stsB(0);
    loadB(32);
    issue(1, 32);
    CP_COMMIT();
    stsB(1);
    if (nIt > 2) loadB(64);

    for (int i = 0; i < nIt; i++) {
        // stage i complete (own thread), then barrier -> visible CTA-wide;
        // barrier also guarantees compute(i-1) done before buffer (i+2)%3
        // [= (i-1)%3] is overwritten below.
        if (i == nIt - 1) CP_WAIT(0); else CP_WAIT(1);
        __syncthreads();

        if (i + 2 < nIt) {
            const int tgt = (i + 2) % 3;
            issue(tgt, (i + 2) * 32);
            CP_COMMIT();
            stsB(tgt);
            if (BIN == 1 && i + 3 < nIt) loadB((i + 3) * 32);
        }

        const uint32_t base = sb + (i % 3) * STG;
#pragma unroll
        for (int kk = 0; kk < 32; kk += 16) {
            uint32_t ah[4][4], bh[4][2];
            const int arw = lane & 15;
            const int acl = kk + (lane >> 4) * 8;
            const int krw = kk + (lane & 15);
            const int nch = (lane >> 4) * 8;

            // B (2 LDSM4T cover 32 n-cols)
#pragma unroll
            for (int ni = 0; ni < 2; ni++) {
                const int nn = nw + ni * 16 + nch;
                const uint32_t bo = (uint32_t)(krw * 256 + ((((nn >> 3) ^ (krw & 7))) << 4));
                LDSM4T(bh[2 * ni][0], bh[2 * ni][1], bh[2 * ni + 1][0], bh[2 * ni + 1][1],
                       base + OFF_B + bo);
            }
            // A
#pragma unroll
            for (int mi = 0; mi < 4; mi++) {
                const int r = mw + mi * 16 + arw;
                const uint32_t ao = (uint32_t)(r * 64 + ((((acl >> 3) ^ ((r >> 1) & 3))) << 4));
                LDSM4(ah[mi][0], ah[mi][1], ah[mi][2], ah[mi][3], base + OFF_A + ao);
            }
#pragma unroll
            for (int mi = 0; mi < 4; mi++)
#pragma unroll
                for (int g = 0; g < 4; g++) MMAH(acc[mi][g], ah[mi], bh[g]);
        }
    }

    // ---- epilogue: BN + ReLU ----
#pragma unroll
    for (int mi = 0; mi < 4; mi++) {
        const int m_t = mBase + mw + mi * 16 + (lane >> 2);
        const int m_b = m_t + 8;
        const float inv_t = gg[m_t] * rsqrtf(vv[m_t] + EPSF);
        const float bt_t  = bb[m_t] - mm[m_t] * inv_t;
        const float inv_b = gg[m_b] * rsqrtf(vv[m_b] + EPSF);
        const float bt_b  = bb[m_b] - mm[m_b] * inv_b;
#pragma unroll
        for (int g = 0; g < 4; g++) {
            const int hw = hw0 + nw + g * 8 + 2 * (lane & 3);
            float vtx = fmaxf(fmaf(acc[mi][g][0], inv_t, bt_t), 0.f);
            float vty = fmaxf(fmaf(acc[mi][g][1], inv_t, bt_t), 0.f);
            float vbx = fmaxf(fmaf(acc[mi][g][2], inv_b, bt_b), 0.f);
            float vby = fmaxf(fmaf(acc[mi][g][3], inv_b, bt_b), 0.f);
            if (BOUT == 1) {
                float* rowT = Cf + (size_t)nbat * cBatch + (size_t)m_t * cRow;
                float* rowB = Cf + (size_t)nbat * cBatch + (size_t)m_b * cRow;
                *(float2*)(rowT + hw) = make_float2(vtx, vty);
                *(float2*)(rowB + hw) = make_float2(vbx, vby);
            } else {
                size_t oT = (size_t)nbat * cBatch + (size_t)m_t * cRow + hw;
                size_t oB = (size_t)nbat * cBatch + (size_t)m_b * cRow + hw;
                *(__half2*)(Ch + oT) = __floats2half2_rn(vtx, vty);
                *(__half2*)(Ch + oB) = __floats2half2_rn(vbx, vby);
            }
        }
    }
}

// ---------------------------------------------------------------------------
// Attention: 256 threads, 2 adjacent pixels/thread; q fp16 plane in,
// ctx fp16 plane out. k/v fp32 in smem.
// ---------------------------------------------------------------------------
__global__ void __launch_bounds__(256) attn_kernel(
    const __half* __restrict__ qh, __half* __restrict__ ch)
{
    __shared__ float k_sh[KCC * KK];
    __shared__ float v_sh[KCC * KK];
    const int pixBase = blockIdx.x * 512;
    const int n = pixBase >> 14;
    for (int i = threadIdx.x; i < KCC * KK; i += 256) {
        k_sh[i] = g_kbuf[(size_t)n * KCC * KK + i];
        v_sh[i] = g_vbuf[(size_t)n * KCC * KK + i];
    }
    __syncthreads();

    const int p0 = pixBase + 2 * threadIdx.x;

    float s0[KK], s1[KK];
#pragma unroll
    for (int j = 0; j < KK; j++) { s0[j] = 0.f; s1[j] = 0.f; }

    for (int c = 0; c < KCC; c++) {
        size_t o = (size_t)c * TOT + p0;
        float2 fq = __half22float2(*(const __half2*)(qh + o));
#pragma unroll
        for (int j = 0; j < KK; j++) {
            const float kc = k_sh[c * KK + j];
            s0[j] = fmaf(fq.x, kc, s0[j]);
            s1[j] = fmaf(fq.y, kc, s1[j]);
        }
    }

    {
        float mx0 = -1e30f, mx1 = -1e30f;
#pragma unroll
        for (int j = 0; j < KK; j++) {
            s0[j] *= 0.0625f; s1[j] *= 0.0625f;
            mx0 = fmaxf(mx0, s0[j]); mx1 = fmaxf(mx1, s1[j]);
        }
        float t0 = 0.f, t1 = 0.f;
#pragma unroll
        for (int j = 0; j < KK; j++) {
            s0[j] = __expf(s0[j] - mx0); t0 += s0[j];
            s1[j] = __expf(s1[j] - mx1); t1 += s1[j];
        }
        const float r0 = 1.f / t0, r1 = 1.f / t1;
#pragma unroll
        for (int j = 0; j < KK; j++) { s0[j] *= r0; s1[j] *= r1; }
    }

    for (int c = 0; c < KCC; c++) {
        float a0 = 0.f, a1 = 0.f;
#pragma unroll
        for (int j = 0; j < KK; j++) {
            const float vc = v_sh[c * KK + j];
            a0 = fmaf(s0[j], vc, a0);
            a1 = fmaf(s1[j], vc, a1);
        }
        size_t o = (size_t)c * TOT + p0;
        *(__half2*)(ch + o) = __floats2half2_rn(a0, a1);
    }
}

// ---------------------------------------------------------------------------
// Launch
// ---------------------------------------------------------------------------
extern "C" void kernel_launch(void* const* d_in, const int* in_sizes, int n_in,
                              void* d_out, int out_size)
{
    const float* x     = (const float*)d_in[0];
    const float* proxy = (const float*)d_in[1];

    const float *w_p1, *w_p2, *w_o1, *w_o2, *w_d, *w_u;
    const float *p1g,*p1b,*p1m,*p1v, *p2g,*p2b,*p2m,*p2v;
    const float *o1g,*o1b,*o1m,*o1v, *o2g,*o2b,*o2m,*o2v;
    const float *dg,*db,*dm,*dv, *ug,*ub,*um,*uv;

    if (in_sizes[3] == KCC * KCC) {
        w_p1=(const float*)d_in[2]; w_p2=(const float*)d_in[3];
        w_o1=(const float*)d_in[4]; w_o2=(const float*)d_in[5];
        w_d =(const float*)d_in[6]; w_u =(const float*)d_in[7];
        p1g=(const float*)d_in[8];  p1b=(const float*)d_in[9];
        p1m=(const float*)d_in[10]; p1v=(const float*)d_in[11];
        p2g=(const float*)d_in[12]; p2b=(const float*)d_in[13];
        p2m=(const float*)d_in[14]; p2v=(const float*)d_in[15];
        o1g=(const float*)d_in[16]; o1b=(const float*)d_in[17];
        o1m=(const float*)d_in[18]; o1v=(const float*)d_in[19];
        o2g=(const float*)d_in[20]; o2b=(const float*)d_in[21];
        o2m=(const float*)d_in[22]; o2v=(const float*)d_in[23];
        dg =(const float*)d_in[24]; db =(const float*)d_in[25];
        dm =(const float*)d_in[26]; dv =(const float*)d_in[27];
        ug =(const float*)d_in[28]; ub =(const float*)d_in[29];
        um =(const float*)d_in[30]; uv =(const float*)d_in[31];
    } else {
        w_p1=(const float*)d_in[2];
        p1g=(const float*)d_in[3];  p1b=(const float*)d_in[4];
        p1m=(const float*)d_in[5];  p1v=(const float*)d_in[6];
        w_p2=(const float*)d_in[7];
        p2g=(const float*)d_in[8];  p2b=(const float*)d_in[9];
        p2m=(const float*)d_in[10]; p2v=(const float*)d_in[11];
        w_o1=(const float*)d_in[12];
        o1g=(const float*)d_in[13]; o1b=(const float*)d_in[14];
        o1m=(const float*)d_in[15]; o1v=(const float*)d_in[16];
        w_o2=(const float*)d_in[17];
        o2g=(const float*)d_in[18]; o2b=(const float*)d_in[19];
        o2m=(const float*)d_in[20]; o2v=(const float*)d_in[21];
        w_d =(const float*)d_in[22];
        dg =(const float*)d_in[23]; db =(const float*)d_in[24];
        dm =(const float*)d_in[25]; dv =(const float*)d_in[26];
        w_u =(const float*)d_in[27];
        ug =(const float*)d_in[28]; ub =(const float*)d_in[29];
        um =(const float*)d_in[30]; uv =(const float*)d_in[31];
    }

    float* out = (float*)d_out;

    __half *t1p,*qp,*cp,*w1p,*w2p,*wup;
    cudaGetSymbolAddress((void**)&t1p, g_t1);
    cudaGetSymbolAddress((void**)&qp,  g_q);
    cudaGetSymbolAddress((void**)&cp,  g_c);
    cudaGetSymbolAddress((void**)&w1p, g_w1);
    cudaGetSymbolAddress((void**)&w2p, g_w2);
    cudaGetSymbolAddress((void**)&wup, g_wu);

    cudaFuncSetAttribute(gemm_mma<1, 0>, cudaFuncAttributeMaxDynamicSharedMemorySize, GEMM_SMEM);
    cudaFuncSetAttribute(gemm_mma<0, 0>, cudaFuncAttributeMaxDynamicSharedMemorySize, GEMM_SMEM);
    cudaFuncSetAttribute(gemm_mma<0, 1>, cudaFuncAttributeMaxDynamicSharedMemorySize, GEMM_SMEM);

    // 0) convert weights to fp16 (tiny)
    cvt16_kernel<<<(KCC * CIN / 4 + 255) / 256, 256>>>(w_p1, w1p, KCC * CIN / 4);
    cvt16_kernel<<<(KCC * KCC / 4 + 255) / 256, 256>>>(w_p2, w2p, KCC * KCC / 4);
    cvt16_kernel<<<(CIN * KCC / 4 + 255) / 256, 256>>>(w_u,  wup, CIN * KCC / 4);

    // 1) proxy path
    proxy1_kernel<<<dim3(8, NB), 256>>>(proxy,
        w_o1, o1g, o1b, o1m, o1v,
        w_d,  dg,  db,  dm,  dv);
    proxy2_kernel<<<dim3(8, NB), 256>>>(w_o2, o2g, o2b, o2m, o2v);

    // 2) t1 = bn_relu(w_p1 @ x)  (x fp32 converted at STS) -> fp16 plane
    gemm_mma<1, 0><<<dim3(KCC / 128, TOT / 128), 256, GEMM_SMEM>>>(
        w1p, CIN,
        nullptr, x, HW, (long)CIN * HW,
        nullptr, t1p, TOT, HW,
        p1g, p1b, p1m, p1v);

    // 3) q = bn_relu(w_p2 @ t1) -> fp16 plane
    gemm_mma<0, 0><<<dim3(KCC / 128, TOT / 128), 256, GEMM_SMEM>>>(
        w2p, KCC,
        t1p, nullptr, TOT, HW,
        nullptr, qp, TOT, HW,
        p2g, p2b, p2m, p2v);

    // 4) attention q -> ctx fp16 plane
    attn_kernel<<<TOT / 512, 256>>>(qp, cp);

    // 5) out = bn_relu(w_u @ ctx) -> fp32 NCHW
    gemm_mma<0, 1><<<dim3(CIN / 128, TOT / 128), 256, GEMM_SMEM>>>(
        wup, KCC,
        cp, nullptr, TOT, HW,
        out, nullptr, HW, (long)CIN * HW,
        ug, ub, um, uv);
}

// round 16
// speedup vs baseline: 1.3340x; 1.1875x over previous
#include <cuda_runtime.h>
#include <cuda_fp16.h>
#include <cstdint>
#include <math.h>

#define NB    8
#define CIN   512
#define KCC   256
#define KK    19
#define KP    32              // padded attention dim for MMA
#define HW    16384
#define TOT   (NB * HW)
#define EPSF  1e-5f

// ---------------------------------------------------------------------------
// Scratch
// ---------------------------------------------------------------------------
__device__ __half g_t1[(size_t)KCC * TOT];
__device__ __half g_q [(size_t)KCC * TOT];
__device__ __half g_pt[(size_t)KP * TOT];      // P^T fp16 [32][TOT], rows 19-31 zero
__device__ __half g_u [NB * CIN * KP];         // U = W_u @ V, fp16 [n][512][32], cols 19-31 zero
__device__ __half g_w1[KCC * CIN];
__device__ __half g_w2[KCC * KCC];
__device__ float  g_tbuf[NB * KCC * KK];
__device__ float  g_kbuf[NB * KCC * KK];
__device__ float  g_vbuf[NB * KCC * KK];

static __device__ __forceinline__ uint32_t smem_u32(const void* p) {
    uint32_t a;
    asm("{ .reg .u64 t; cvta.to.shared.u64 t, %1; cvt.u32.u64 %0, t; }"
        : "=r"(a) : "l"(p));
    return a;
}

#define LDSM4(r0, r1, r2, r3, addr) \
    asm volatile("ldmatrix.sync.aligned.m8n8.x4.shared.b16 {%0,%1,%2,%3}, [%4];" \
                 : "=r"(r0), "=r"(r1), "=r"(r2), "=r"(r3) : "r"(addr))

#define LDSM4T(r0, r1, r2, r3, addr) \
    asm volatile("ldmatrix.sync.aligned.m8n8.x4.trans.shared.b16 {%0,%1,%2,%3}, [%4];" \
                 : "=r"(r0), "=r"(r1), "=r"(r2), "=r"(r3) : "r"(addr))

#define MMAH(d, a, b) \
    asm volatile("mma.sync.aligned.m16n8k16.row.col.f32.f16.f16.f32 " \
                 "{%0,%1,%2,%3}, {%4,%5,%6,%7}, {%8,%9}, {%0,%1,%2,%3};" \
                 : "+f"((d)[0]), "+f"((d)[1]), "+f"((d)[2]), "+f"((d)[3]) \
                 : "r"((a)[0]), "r"((a)[1]), "r"((a)[2]), "r"((a)[3]), \
                   "r"((b)[0]), "r"((b)[1]))

#define CP_ASYNC16(dst, src) \
    asm volatile("cp.async.cg.shared.global [%0], [%1], 16;" :: "r"(dst), "l"(src))
#define CP_COMMIT()  asm volatile("cp.async.commit_group;")
#define CP_WAIT(n)   asm volatile("cp.async.wait_group %0;" :: "n"(n))

static __device__ __forceinline__ uint32_t h2u(__half2 h) {
    return *reinterpret_cast<uint32_t*>(&h);
}
static __device__ __forceinline__ uint4 cvt8(const float4& a, const float4& b) {
    __half2 h0 = __floats2half2_rn(a.x, a.y);
    __half2 h1 = __floats2half2_rn(a.z, a.w);
    __half2 h2 = __floats2half2_rn(b.x, b.y);
    __half2 h3 = __floats2half2_rn(b.z, b.w);
    return make_uint4(h2u(h0), h2u(h1), h2u(h2), h2u(h3));
}

// ---------------------------------------------------------------------------
// fp32 -> fp16 plane (weights only; tiny)
// ---------------------------------------------------------------------------
__global__ void __launch_bounds__(256) cvt16_kernel(
    const float* __restrict__ s, __half* __restrict__ h, size_t n4)
{
    size_t idx = (size_t)blockIdx.x * 256 + threadIdx.x;
    if (idx >= n4) return;
    float4 v = ((const float4*)s)[idx];
    ((__half2*)h)[2 * idx]     = __floats2half2_rn(v.x, v.y);
    ((__half2*)h)[2 * idx + 1] = __floats2half2_rn(v.z, v.w);
}

// ---------------------------------------------------------------------------
// Proxy stage 1: t = bn_relu(w_o1 @ proxy_n), v = bn_relu(w_d @ proxy_n)
// ---------------------------------------------------------------------------
__global__ void __launch_bounds__(256) proxy1_kernel(
    const float* __restrict__ proxy,
    const float* __restrict__ w_o1, const float* __restrict__ o1g,
    const float* __restrict__ o1b,  const float* __restrict__ o1m,
    const float* __restrict__ o1v,
    const float* __restrict__ w_d,  const float* __restrict__ dgv,
    const float* __restrict__ dbv,  const float* __restrict__ dmv,
    const float* __restrict__ dvv)
{
    __shared__ float p_sh[CIN * KK];
    const int n   = blockIdx.y;
    const int ch0 = blockIdx.x * 32;
    const float* p = proxy + (size_t)n * CIN * KK;
    for (int i = threadIdx.x; i < CIN * KK; i += 256) p_sh[i] = p[i];
    __syncthreads();

    const int chl = threadIdx.x >> 3;
    const int jg  = threadIdx.x & 7;
    const int ch  = ch0 + chl;

    float a1[3] = {0.f, 0.f, 0.f}, av[3] = {0.f, 0.f, 0.f};
    const float* w1r = w_o1 + (size_t)ch * CIN;
    const float* wdr = w_d  + (size_t)ch * CIN;
    for (int c = 0; c < CIN; c++) {
        const float w1 = __ldg(&w1r[c]);
        const float wd = __ldg(&wdr[c]);
        const float* pc = p_sh + c * KK;
#pragma unroll
        for (int u = 0; u < 3; u++) {
            const int j = jg + 8 * u;
            if (j < KK) {
                const float pv = pc[j];
                a1[u] = fmaf(w1, pv, a1[u]);
                av[u] = fmaf(wd, pv, av[u]);
            }
        }
    }
    {
        const float inv = o1g[ch] * rsqrtf(o1v[ch] + EPSF);
        const float bt  = o1b[ch] - o1m[ch] * inv;
#pragma unroll
        for (int u = 0; u < 3; u++) {
            const int j = jg + 8 * u;
            if (j < KK)
                g_tbuf[((size_t)n * KCC + ch) * KK + j] = fmaxf(fmaf(a1[u], inv, bt), 0.f);
        }
    }
    {
        const float inv = dgv[ch] * rsqrtf(dvv[ch] + EPSF);
        const float bt  = dbv[ch] - dmv[ch] * inv;
#pragma unroll
        for (int u = 0; u < 3; u++) {
            const int j = jg + 8 * u;
            if (j < KK)
                g_vbuf[((size_t)n * KCC + ch) * KK + j] = fmaxf(fmaf(av[u], inv, bt), 0.f);
        }
    }
}

// ---------------------------------------------------------------------------
// Proxy stage 2: k = bn_relu(w_o2 @ t_n)
// ---------------------------------------------------------------------------
__global__ void __launch_bounds__(256) proxy2_kernel(
    const float* __restrict__ w_o2, const float* __restrict__ o2g,
    const float* __restrict__ o2b,  const float* __restrict__ o2m,
    const float* __restrict__ o2v)
{
    __shared__ float t_sh[KCC * KK];
    const int n   = blockIdx.y;
    const int ch0 = blockIdx.x * 32;
    for (int i = threadIdx.x; i < KCC * KK; i += 256)
        t_sh[i] = g_tbuf[(size_t)n * KCC * KK + i];
    __syncthreads();

    const int chl = threadIdx.x >> 3;
    const int jg  = threadIdx.x & 7;
    const int ch  = ch0 + chl;

    float a2[3] = {0.f, 0.f, 0.f};
    const float* w2r = w_o2 + (size_t)ch * KCC;
    for (int c = 0; c < KCC; c++) {
        const float w2 = __ldg(&w2r[c]);
        const float* tc = t_sh + c * KK;
#pragma unroll
        for (int u = 0; u < 3; u++) {
            const int j = jg + 8 * u;
            if (j < KK) a2[u] = fmaf(w2, tc[j], a2[u]);
        }
    }
    const float inv = o2g[ch] * rsqrtf(o2v[ch] + EPSF);
    const float bt  = o2b[ch] - o2m[ch] * inv;
#pragma unroll
    for (int u = 0; u < 3; u++) {
        const int j = jg + 8 * u;
        if (j < KK)
            g_kbuf[((size_t)n * KCC + ch) * KK + j] = fmaxf(fmaf(a2[u], inv, bt), 0.f);
    }
}

// ---------------------------------------------------------------------------
// U kernel: U[n][512][32] (fp16) = W_u[512][256] @ v_n[256][19], cols 19-31 = 0.
// grid (16 ch-tiles, NB), 256 threads; thread = (ch_local, jg), j = jg + 8u.
// ---------------------------------------------------------------------------
__global__ void __launch_bounds__(256) ukernel(const float* __restrict__ w_u)
{
    __shared__ float v_sh[KCC * KK];
    const int n   = blockIdx.y;
    const int ch0 = blockIdx.x * 32;
    for (int i = threadIdx.x; i < KCC * KK; i += 256)
        v_sh[i] = g_vbuf[(size_t)n * KCC * KK + i];
    __syncthreads();

    const int chl = threadIdx.x >> 3;
    const int jg  = threadIdx.x & 7;
    const int ch  = ch0 + chl;

    float acc[4] = {0.f, 0.f, 0.f, 0.f};
    const float* wr = w_u + (size_t)ch * KCC;
    for (int c = 0; c < KCC; c++) {
        const float w = __ldg(&wr[c]);
        const float* vc = v_sh + c * KK;
#pragma unroll
        for (int u = 0; u < 4; u++) {
            const int j = jg + 8 * u;
            if (j < KK) acc[u] = fmaf(w, vc[j], acc[u]);
        }
    }
    __half* ur = g_u + ((size_t)n * CIN + ch) * KP;
#pragma unroll
    for (int u = 0; u < 4; u++) {
        const int j = jg + 8 * u;
        if (j < KP)
            ur[j] = __float2half_rn(j < KK ? acc[u] : 0.f);
    }
}

// ---------------------------------------------------------------------------
// HMMA fp16 GEMM: D = bn_relu( A @ B ), 3-stage pipeline, 1 sync/iter.
// BM=128 BN=128 BK=32, 256 threads, 2 CTAs/SM, warp tile 64x32.
// A is per-batch offset by aBatch (0 for shared weights).
// BIN 0: B fp16 (cp.async); 1: B fp32 (reg load, STS convert).
// BOUT 0: fp16 plane out;   1: fp32 out.
// ---------------------------------------------------------------------------
#define OFF_A  0
#define OFF_B  8192
#define STG    16384
#define GEMM_SMEM (3 * STG)

template <int BIN, int BOUT>
__global__ void __launch_bounds__(256, 2) gemm_mma(
    const __half* __restrict__ A, long aBatch, int KT,
    const __half* __restrict__ Bh, const float* __restrict__ Bf,
    int bRow, long bBatch,
    float* __restrict__ Cf, __half* __restrict__ Ch,
    int cRow, long cBatch,
    const float* __restrict__ gg, const float* __restrict__ bb,
    const float* __restrict__ mm, const float* __restrict__ vv)
{
    extern __shared__ __align__(128) unsigned char sm[];
    const uint32_t sb = smem_u32(sm);

    const int tid  = threadIdx.x;
    const int lane = tid & 31;
    const int w    = tid >> 5;
    const int mw   = (w >> 2) * 64;
    const int nw   = (w & 3) * 32;

    const int mBase = blockIdx.x * 128;
    const int nBase = blockIdx.y * 128;
    const int nbat  = nBase >> 14;
    const int hw0   = nBase & (HW - 1);

    const __half* Ap  = A + (size_t)nbat * aBatch;
    const __half* Bph = (BIN == 0) ? Bh + (size_t)nbat * bBatch + hw0 : nullptr;
    const float*  Bpf = (BIN == 1) ? Bf + (size_t)nbat * bBatch + hw0 : nullptr;

    const int arow = tid >> 1;
    const int aq0  = (tid & 1) * 2;
    const int bk   = tid >> 3;
    const int bu0  = (tid & 7) * 2;

    float acc[4][4][4];
#pragma unroll
    for (int i = 0; i < 4; i++)
#pragma unroll
        for (int g = 0; g < 4; g++)
#pragma unroll
            for (int r = 0; r < 4; r++) acc[i][g][r] = 0.f;

    const int nIt = KT / 32;

    float4 pbf[4];

    auto loadB = [&](int k0) {
        if (BIN == 1) {
#pragma unroll
            for (int j = 0; j < 2; j++) {
                const float* src = Bpf + (size_t)(k0 + bk) * bRow + (bu0 + j) * 8;
                pbf[2 * j]     = *(const float4*)src;
                pbf[2 * j + 1] = *(const float4*)(src + 4);
            }
        }
    };
    auto stsB = [&](int buf) {
        if (BIN == 1) {
#pragma unroll
            for (int j = 0; j < 2; j++) {
                const int u = bu0 + j;
                const uint32_t off = (uint32_t)(bk * 256 + ((u ^ (bk & 7)) << 4));
                *(uint4*)(sm + buf * STG + OFF_B + off) = cvt8(pbf[2 * j], pbf[2 * j + 1]);
            }
        }
    };
    auto issue = [&](int buf, int k0) {
        const uint32_t base = sb + buf * STG;
        const __half* ar = Ap + (size_t)(mBase + arow) * KT + k0;
#pragma unroll
        for (int j = 0; j < 2; j++) {
            const int q = aq0 + j;
            const uint32_t off = (uint32_t)(arow * 64 + ((q ^ ((arow >> 1) & 3)) << 4));
            CP_ASYNC16(base + OFF_A + off, ar + q * 8);
        }
        if (BIN == 0) {
#pragma unroll
            for (int j = 0; j < 2; j++) {
                const int u = bu0 + j;
                const uint32_t off = (uint32_t)(bk * 256 + ((u ^ (bk & 7)) << 4));
                CP_ASYNC16(base + OFF_B + off, Bph + (size_t)(k0 + bk) * bRow + u * 8);
            }
        }
    };

    // prologue: stages 0 and (if any) 1 — guarded for short-K kernels
    loadB(0);
    issue(0, 0);
    CP_COMMIT();
    stsB(0);
    if (nIt > 1) {
        loadB(32);
        issue(1, 32);
        CP_COMMIT();
        stsB(1);
        if (nIt > 2) loadB(64);
    }

    for (int i = 0; i < nIt; i++) {
        if (i == nIt - 1) CP_WAIT(0); else CP_WAIT(1);
        __syncthreads();

        if (i + 2 < nIt) {
            const int tgt = (i + 2) % 3;
            issue(tgt, (i + 2) * 32);
            CP_COMMIT();
            stsB(tgt);
            if (BIN == 1 && i + 3 < nIt) loadB((i + 3) * 32);
        }

        const uint32_t base = sb + (i % 3) * STG;
#pragma unroll
        for (int kk = 0; kk < 32; kk += 16) {
            uint32_t ah[4][4], bh[4][2];
            const int arw = lane & 15;
            const int acl = kk + (lane >> 4) * 8;
            const int krw = kk + (lane & 15);
            const int nch = (lane >> 4) * 8;

#pragma unroll
            for (int ni = 0; ni < 2; ni++) {
                const int nn = nw + ni * 16 + nch;
                const uint32_t bo = (uint32_t)(krw * 256 + ((((nn >> 3) ^ (krw & 7))) << 4));
                LDSM4T(bh[2 * ni][0], bh[2 * ni][1], bh[2 * ni + 1][0], bh[2 * ni + 1][1],
                       base + OFF_B + bo);
            }
#pragma unroll
            for (int mi = 0; mi < 4; mi++) {
                const int r = mw + mi * 16 + arw;
                const uint32_t ao = (uint32_t)(r * 64 + ((((acl >> 3) ^ ((r >> 1) & 3))) << 4));
                LDSM4(ah[mi][0], ah[mi][1], ah[mi][2], ah[mi][3], base + OFF_A + ao);
            }
#pragma unroll
            for (int mi = 0; mi < 4; mi++)
#pragma unroll
                for (int g = 0; g < 4; g++) MMAH(acc[mi][g], ah[mi], bh[g]);
        }
    }

    // ---- epilogue: BN + ReLU ----
#pragma unroll
    for (int mi = 0; mi < 4; mi++) {
        const int m_t = mBase + mw + mi * 16 + (lane >> 2);
        const int m_b = m_t + 8;
        const float inv_t = gg[m_t] * rsqrtf(vv[m_t] + EPSF);
        const float bt_t  = bb[m_t] - mm[m_t] * inv_t;
        const float inv_b = gg[m_b] * rsqrtf(vv[m_b] + EPSF);
        const float bt_b  = bb[m_b] - mm[m_b] * inv_b;
#pragma unroll
        for (int g = 0; g < 4; g++) {
            const int hw = hw0 + nw + g * 8 + 2 * (lane & 3);
            float vtx = fmaxf(fmaf(acc[mi][g][0], inv_t, bt_t), 0.f);
            float vty = fmaxf(fmaf(acc[mi][g][1], inv_t, bt_t), 0.f);
            float vbx = fmaxf(fmaf(acc[mi][g][2], inv_b, bt_b), 0.f);
            float vby = fmaxf(fmaf(acc[mi][g][3], inv_b, bt_b), 0.f);
            if (BOUT == 1) {
                float* rowT = Cf + (size_t)nbat * cBatch + (size_t)m_t * cRow;
                float* rowB = Cf + (size_t)nbat * cBatch + (size_t)m_b * cRow;
                *(float2*)(rowT + hw) = make_float2(vtx, vty);
                *(float2*)(rowB + hw) = make_float2(vbx, vby);
            } else {
                size_t oT = (size_t)nbat * cBatch + (size_t)m_t * cRow + hw;
                size_t oB = (size_t)nbat * cBatch + (size_t)m_b * cRow + hw;
                *(__half2*)(Ch + oT) = __floats2half2_rn(vtx, vty);
                *(__half2*)(Ch + oB) = __floats2half2_rn(vbx, vby);
            }
        }
    }
}

// ---------------------------------------------------------------------------
// Attention (QK + softmax only): q fp16 plane in, P^T fp16 [32][TOT] out
// (rows 19-31 zeroed). k fp32 in smem. 2 adjacent pixels per thread.
// ---------------------------------------------------------------------------
__global__ void __launch_bounds__(256) attn_kernel(
    const __half* __restrict__ qh, __half* __restrict__ pt)
{
    __shared__ float k_sh[KCC * KK];
    const int pixBase = blockIdx.x * 512;
    const int n = pixBase >> 14;
    for (int i = threadIdx.x; i < KCC * KK; i += 256)
        k_sh[i] = g_kbuf[(size_t)n * KCC * KK + i];
    __syncthreads();

    const int p0 = pixBase + 2 * threadIdx.x;

    float s0[KK], s1[KK];
#pragma unroll
    for (int j = 0; j < KK; j++) { s0[j] = 0.f; s1[j] = 0.f; }

    for (int c = 0; c < KCC; c++) {
        size_t o = (size_t)c * TOT + p0;
        float2 fq = __half22float2(*(const __half2*)(qh + o));
#pragma unroll
        for (int j = 0; j < KK; j++) {
            const float kc = k_sh[c * KK + j];
            s0[j] = fmaf(fq.x, kc, s0[j]);
            s1[j] = fmaf(fq.y, kc, s1[j]);
        }
    }

    {
        float mx0 = -1e30f, mx1 = -1e30f;
#pragma unroll
        for (int j = 0; j < KK; j++) {
            s0[j] *= 0.0625f; s1[j] *= 0.0625f;
            mx0 = fmaxf(mx0, s0[j]); mx1 = fmaxf(mx1, s1[j]);
        }
        float t0 = 0.f, t1 = 0.f;
#pragma unroll
        for (int j = 0; j < KK; j++) {
            s0[j] = __expf(s0[j] - mx0); t0 += s0[j];
            s1[j] = __expf(s1[j] - mx1); t1 += s1[j];
        }
        const float r0 = 1.f / t0, r1 = 1.f / t1;
#pragma unroll
        for (int j = 0; j < KK; j++) { s0[j] *= r0; s1[j] *= r1; }
    }

#pragma unroll
    for (int j = 0; j < KK; j++)
        *(__half2*)(pt + (size_t)j * TOT + p0) = __floats2half2_rn(s0[j], s1[j]);
    const __half2 z2 = __floats2half2_rn(0.f, 0.f);
#pragma unroll
    for (int j = KK; j < KP; j++)
        *(__half2*)(pt + (size_t)j * TOT + p0) = z2;
}

// ---------------------------------------------------------------------------
// Launch
// ---------------------------------------------------------------------------
extern "C" void kernel_launch(void* const* d_in, const int* in_sizes, int n_in,
                              void* d_out, int out_size)
{
    const float* x     = (const float*)d_in[0];
    const float* proxy = (const float*)d_in[1];

    const float *w_p1, *w_p2, *w_o1, *w_o2, *w_d, *w_u;
    const float *p1g,*p1b,*p1m,*p1v, *p2g,*p2b,*p2m,*p2v;
    const float *o1g,*o1b,*o1m,*o1v, *o2g,*o2b,*o2m,*o2v;
    const float *dg,*db,*dm,*dv, *ug,*ub,*um,*uv;

    if (in_sizes[3] == KCC * KCC) {
        w_p1=(const float*)d_in[2]; w_p2=(const float*)d_in[3];
        w_o1=(const float*)d_in[4]; w_o2=(const float*)d_in[5];
        w_d =(const float*)d_in[6]; w_u =(const float*)d_in[7];
        p1g=(const float*)d_in[8];  p1b=(const float*)d_in[9];
        p1m=(const float*)d_in[10]; p1v=(const float*)d_in[11];
        p2g=(const float*)d_in[12]; p2b=(const float*)d_in[13];
        p2m=(const float*)d_in[14]; p2v=(const float*)d_in[15];
        o1g=(const float*)d_in[16]; o1b=(const float*)d_in[17];
        o1m=(const float*)d_in[18]; o1v=(const float*)d_in[19];
        o2g=(const float*)d_in[20]; o2b=(const float*)d_in[21];
        o2m=(const float*)d_in[22]; o2v=(const float*)d_in[23];
        dg =(const float*)d_in[24]; db =(const float*)d_in[25];
        dm =(const float*)d_in[26]; dv =(const float*)d_in[27];
        ug =(const float*)d_in[28]; ub =(const float*)d_in[29];
        um =(const float*)d_in[30]; uv =(const float*)d_in[31];
    } else {
        w_p1=(const float*)d_in[2];
        p1g=(const float*)d_in[3];  p1b=(const float*)d_in[4];
        p1m=(const float*)d_in[5];  p1v=(const float*)d_in[6];
        w_p2=(const float*)d_in[7];
        p2g=(const float*)d_in[8];  p2b=(const float*)d_in[9];
        p2m=(const float*)d_in[10]; p2v=(const float*)d_in[11];
        w_o1=(const float*)d_in[12];
        o1g=(const float*)d_in[13]; o1b=(const float*)d_in[14];
        o1m=(const float*)d_in[15]; o1v=(const float*)d_in[16];
        w_o2=(const float*)d_in[17];
        o2g=(const float*)d_in[18]; o2b=(const float*)d_in[19];
        o2m=(const float*)d_in[20]; o2v=(const float*)d_in[21];
        w_d =(const float*)d_in[22];
        dg =(const float*)d_in[23]; db =(const float*)d_in[24];
        dm =(const float*)d_in[25]; dv =(const float*)d_in[26];
        w_u =(const float*)d_in[27];
        ug =(const float*)d_in[28]; ub =(const float*)d_in[29];
        um =(const float*)d_in[30]; uv =(const float*)d_in[31];
    }

    float* out = (float*)d_out;

    __half *t1p,*qp,*ptp,*up,*w1p,*w2p;
    cudaGetSymbolAddress((void**)&t1p, g_t1);
    cudaGetSymbolAddress((void**)&qp,  g_q);
    cudaGetSymbolAddress((void**)&ptp, g_pt);
    cudaGetSymbolAddress((void**)&up,  g_u);
    cudaGetSymbolAddress((void**)&w1p, g_w1);
    cudaGetSymbolAddress((void**)&w2p, g_w2);

    cudaFuncSetAttribute(gemm_mma<1, 0>, cudaFuncAttributeMaxDynamicSharedMemorySize, GEMM_SMEM);
    cudaFuncSetAttribute(gemm_mma<0, 0>, cudaFuncAttributeMaxDynamicSharedMemorySize, GEMM_SMEM);
    cudaFuncSetAttribute(gemm_mma<0, 1>, cudaFuncAttributeMaxDynamicSharedMemorySize, GEMM_SMEM);

    // 0) convert weights to fp16 (tiny)
    cvt16_kernel<<<(KCC * CIN / 4 + 255) / 256, 256>>>(w_p1, w1p, KCC * CIN / 4);
    cvt16_kernel<<<(KCC * KCC / 4 + 255) / 256, 256>>>(w_p2, w2p, KCC * KCC / 4);

    // 1) proxy path: t,v then k; then U = W_u @ V
    proxy1_kernel<<<dim3(8, NB), 256>>>(proxy,
        w_o1, o1g, o1b, o1m, o1v,
        w_d,  dg,  db,  dm,  dv);
    proxy2_kernel<<<dim3(8, NB), 256>>>(w_o2, o2g, o2b, o2m, o2v);
    ukernel<<<dim3(16, NB), 256>>>(w_u);

    // 2) t1 = bn_relu(w_p1 @ x)  (x fp32 converted at STS) -> fp16 plane
    gemm_mma<1, 0><<<dim3(KCC / 128, TOT / 128), 256, GEMM_SMEM>>>(
        w1p, 0, CIN,
        nullptr, x, HW, (long)CIN * HW,
        nullptr, t1p, TOT, HW,
        p1g, p1b, p1m, p1v);

    // 3) q = bn_relu(w_p2 @ t1) -> fp16 plane
    gemm_mma<0, 0><<<dim3(KCC / 128, TOT / 128), 256, GEMM_SMEM>>>(
        w2p, 0, KCC,
        t1p, nullptr, TOT, HW,
        nullptr, qp, TOT, HW,
        p2g, p2b, p2m, p2v);

    // 4) attention: q -> P^T fp16 [32][TOT]
    attn_kernel<<<TOT / 512, 256>>>(qp, ptp);

    // 5) out = bn_relu(U_n @ P^T) -> fp32 NCHW   (K = 32)
    gemm_mma<0, 1><<<dim3(CIN / 128, TOT / 128), 256, GEMM_SMEM>>>(
        up, (long)CIN * KP, KP,
        ptp, nullptr, TOT, HW,
        out, nullptr, HW, (long)CIN * HW,
        ug, ub, um, uv);
}